// round 1
// baseline (speedup 1.0000x reference)
#include <cuda_runtime.h>

// EquivariantLayerNorm: dim=1184 = 256(l=0) + 384(l=1) + 320(l=2) + 224(l=3)
// Group boundaries in float4 units: [0,64) g0, [64,160) g1, [160,240) g2, [240,296) g3.
#define DIM   1184
#define VECS  296
#define NTHR  256
#define EPSV  1e-5f

__device__ float g_wfull[DIM];   // weight[irrep_idx[j]] per feature
__device__ float g_bfull[DIM];   // bias scattered to scalar_indices, else 0

__global__ void eln_prologue_w(const float* __restrict__ weight,
                               const int*   __restrict__ irrep_idx) {
    int j = blockIdx.x * blockDim.x + threadIdx.x;
    if (j < DIM) {
        g_wfull[j] = weight[irrep_idx[j]];
        g_bfull[j] = 0.0f;
    }
}

__global__ void eln_prologue_b(const float* __restrict__ bias,
                               const int*   __restrict__ scalar_indices,
                               int nscal) {
    int i = blockIdx.x * blockDim.x + threadIdx.x;
    if (i < nscal) g_bfull[scalar_indices[i]] = bias[i];
}

__device__ __forceinline__ int group_of_vec(int v) {
    return (v < 64) ? 0 : (v < 160) ? 1 : (v < 240) ? 2 : 3;
}

__global__ __launch_bounds__(NTHR, 8)
void eln_kernel(const float4* __restrict__ x, float4* __restrict__ out) {
    const int row = blockIdx.x;
    const int tid = threadIdx.x;
    const float4* __restrict__ xr  = x   + (size_t)row * VECS;
    float4* __restrict__       orw = out + (size_t)row * VECS;

    // ---- load row into registers (<= 2 float4 per thread) ----
    float4 v0 = xr[tid];
    const bool has2 = (tid < (VECS - NTHR));           // tid < 40
    float4 v1 = make_float4(0.f, 0.f, 0.f, 0.f);
    if (has2) v1 = xr[NTHR + tid];

    // ---- partials: scalar sum + per-group sum of squares ----
    const int g0 = group_of_vec(tid);
    const int warpBase = tid & ~31;
    const int gA = group_of_vec(warpBase);
    const int gB = group_of_vec(warpBase + 31);        // != gA only for warp 7

    float ssum = (g0 == 0) ? (v0.x + v0.y + v0.z + v0.w) : 0.f;
    float d0 = v0.x * v0.x + v0.y * v0.y + v0.z * v0.z + v0.w * v0.w;
    float qx = (g0 == gA) ? d0 : 0.f;                  // contribution to group gA
    float qy = (gB != gA && g0 == gB) ? d0 : 0.f;      // contribution to group gB (warp 7)
    float q3b = 0.f;                                   // second vec: always group 3
    if (has2) q3b = v1.x * v1.x + v1.y * v1.y + v1.z * v1.z + v1.w * v1.w;

    // ---- warp reductions ----
    #pragma unroll
    for (int o = 16; o; o >>= 1) {
        ssum += __shfl_xor_sync(0xffffffffu, ssum, o);
        qx   += __shfl_xor_sync(0xffffffffu, qx,   o);
        qy   += __shfl_xor_sync(0xffffffffu, qy,   o);
        q3b  += __shfl_xor_sync(0xffffffffu, q3b,  o);
    }

    __shared__ float sh[5];   // [0]=scalar sum, [1..4]=group sumsq
    if (tid < 5) sh[tid] = 0.f;
    __syncthreads();

    if ((tid & 31) == 0) {
        if (gA == 0) atomicAdd(&sh[0], ssum);
        atomicAdd(&sh[1 + gA], qx);
        if (gB != gA) atomicAdd(&sh[1 + gB], qy);
        if (tid < 64) atomicAdd(&sh[4], q3b);          // warps 0,1 carry second-vec g3 part
    }
    __syncthreads();

    // ---- stats ----
    const float m    = sh[0] * (1.0f / 256.0f);
    // var of scalar group via E[x^2] - m^2 (exact-arithmetic identity with mean subtraction)
    const float var0 = sh[1] * (1.0f / 256.0f) - m * m;
    const float var1 = sh[2] * (1.0f / 384.0f);
    const float var2 = sh[3] * (1.0f / 320.0f);
    const float var3 = sh[4] * (1.0f / 224.0f);

    const float r0 = rsqrtf(var0 + EPSV);
    const float r1 = rsqrtf(var1 + EPSV);
    const float r2 = rsqrtf(var2 + EPSV);
    const float r3 = rsqrtf(var3 + EPSV);

    const float rg  = (g0 == 0) ? r0 : (g0 == 1) ? r1 : (g0 == 2) ? r2 : r3;
    const float sub = (g0 == 0) ? m : 0.f;

    // ---- write pass ----
    const float4* __restrict__ wf = (const float4*)g_wfull;
    const float4* __restrict__ bf = (const float4*)g_bfull;

    {
        float4 w = wf[tid], b = bf[tid], o;
        o.x = (v0.x - sub) * rg * w.x + b.x;
        o.y = (v0.y - sub) * rg * w.y + b.y;
        o.z = (v0.z - sub) * rg * w.z + b.z;
        o.w = (v0.w - sub) * rg * w.w + b.w;
        orw[tid] = o;
    }
    if (has2) {
        float4 w = wf[NTHR + tid], b = bf[NTHR + tid], o;
        o.x = v1.x * r3 * w.x + b.x;
        o.y = v1.y * r3 * w.y + b.y;
        o.z = v1.z * r3 * w.z + b.z;
        o.w = v1.w * r3 * w.w + b.w;
        orw[NTHR + tid] = o;
    }
}

extern "C" void kernel_launch(void* const* d_in, const int* in_sizes, int n_in,
                              void* d_out, int out_size) {
    const float* x              = (const float*)d_in[0];
    const float* weight         = (const float*)d_in[1];
    const float* bias           = (const float*)d_in[2];
    // d_in[3] = group_idx (unused: boundaries compile-time)
    const int*   irrep_idx      = (const int*)d_in[4];
    const int*   scalar_indices = (const int*)d_in[5];
    // d_in[6] = scalar_group (single scalar group)
    float* out = (float*)d_out;

    const int n_rows = in_sizes[0] / DIM;
    const int nscal  = in_sizes[5];

    eln_prologue_w<<<(DIM + 255) / 256, 256>>>(weight, irrep_idx);
    eln_prologue_b<<<(nscal + 255) / 256, 256>>>(bias, scalar_indices, nscal);
    eln_kernel<<<n_rows, NTHR>>>((const float4*)x, (float4*)out);
}